// round 2
// baseline (speedup 1.0000x reference)
#include <cuda_runtime.h>
#include <cstdint>

#define BATCH 64
#define TSEQ  1024
#define DK    64
#define MASK_FILL (-4294967295.0f)   // -2^32 + 1

// ---------------------------------------------------------------------------
// Kernel 1: logits = QK^T/8 - gf, masked fill, softmax, * query_mask -> attn
// Block: 256 threads, handles 32 query rows of one batch.
// Dynamic smem: sLog[32][1024] + sQ[32][64] + sKt[64][68]
// ---------------------------------------------------------------------------
#define K1_ROWS 32
#define KT_PAD  68
#define SMEM1_FLOATS (K1_ROWS*TSEQ + K1_ROWS*DK + DK*KT_PAD)

__global__ __launch_bounds__(256, 1)
void attn_softmax_kernel(const float* __restrict__ K,
                         const float* __restrict__ Q,
                         const int*   __restrict__ mask,     // bool serialized as int32
                         const float* __restrict__ qmask,
                         const float* __restrict__ gf,
                         float* __restrict__ attn_out)
{
    extern __shared__ float smem[];
    float* sLog = smem;                         // 32*1024
    float* sQ   = sLog + K1_ROWS * TSEQ;        // 32*64
    float* sKt  = sQ + K1_ROWS * DK;            // 64*68 (transposed K tile)

    const int b   = blockIdx.y;
    const int q0  = blockIdx.x * K1_ROWS;
    const int tid = threadIdx.x;

    // load Q tile [32][64], coalesced
    {
        const float* Qb = Q + ((size_t)b * TSEQ + q0) * DK;
        #pragma unroll
        for (int i = 0; i < (K1_ROWS * DK) / 256; ++i)
            sQ[tid + 256 * i] = Qb[tid + 256 * i];
    }

    const int rg = tid >> 4;       // 0..15 row group (2 rows each)
    const int cg = tid & 15;       // 0..15 col group (4 cols each)
    const int qr = rg * 2;
    const int kc = cg * 4;

    __syncthreads();

    for (int kt = 0; kt < TSEQ / 64; ++kt) {
        const int k0 = kt * 64;
        // load K tile transposed: sKt[d][k], 64x64 source
        const float* Kb = K + ((size_t)b * TSEQ + k0) * DK;
        #pragma unroll
        for (int i = 0; i < 4; ++i) {
            int e  = tid + 256 * i;      // float4 index 0..1023
            int kk = e >> 4;             // key within tile
            int d4 = (e & 15) * 4;       // dim start
            float4 v = *(const float4*)(Kb + (size_t)kk * DK + d4);
            sKt[(d4 + 0) * KT_PAD + kk] = v.x;
            sKt[(d4 + 1) * KT_PAD + kk] = v.y;
            sKt[(d4 + 2) * KT_PAD + kk] = v.z;
            sKt[(d4 + 3) * KT_PAD + kk] = v.w;
        }
        __syncthreads();

        float acc00 = 0.f, acc01 = 0.f, acc02 = 0.f, acc03 = 0.f;
        float acc10 = 0.f, acc11 = 0.f, acc12 = 0.f, acc13 = 0.f;
        #pragma unroll
        for (int d = 0; d < DK; ++d) {
            float qa = sQ[qr * DK + d];
            float qb = sQ[(qr + 1) * DK + d];
            float4 kv = *(const float4*)(sKt + d * KT_PAD + kc);
            acc00 += qa * kv.x; acc01 += qa * kv.y;
            acc02 += qa * kv.z; acc03 += qa * kv.w;
            acc10 += qb * kv.x; acc11 += qb * kv.y;
            acc12 += qb * kv.z; acc13 += qb * kv.w;
        }

        // epilogue: scale, subtract gaussian, mask fill, stash in sLog
        #pragma unroll
        for (int j = 0; j < 2; ++j) {
            const int row = qr + j;
            size_t base = ((size_t)b * TSEQ + (q0 + row)) * TSEQ + k0 + kc;
            float4 g = *(const float4*)(gf + base);
            int4   m = *(const int4*)(mask + base);
            float a0 = j ? acc10 : acc00;
            float a1 = j ? acc11 : acc01;
            float a2 = j ? acc12 : acc02;
            float a3 = j ? acc13 : acc03;
            float4 s;
            s.x = m.x ? MASK_FILL : fmaf(a0, 0.125f, -g.x);
            s.y = m.y ? MASK_FILL : fmaf(a1, 0.125f, -g.y);
            s.z = m.z ? MASK_FILL : fmaf(a2, 0.125f, -g.z);
            s.w = m.w ? MASK_FILL : fmaf(a3, 0.125f, -g.w);
            *(float4*)(sLog + row * TSEQ + k0 + kc) = s;
        }
        __syncthreads();
    }

    // softmax: warp w handles rows 4w..4w+3; each lane owns 8 float4 chunks
    const int w    = tid >> 5;
    const int lane = tid & 31;
    for (int rr = 0; rr < 4; ++rr) {
        const int r = w * 4 + rr;
        float4 p[8];
        float mx = -3.4e38f;
        #pragma unroll
        for (int j = 0; j < 8; ++j) {
            p[j] = *(const float4*)(sLog + r * TSEQ + (lane + 32 * j) * 4);
            mx = fmaxf(mx, fmaxf(fmaxf(p[j].x, p[j].y), fmaxf(p[j].z, p[j].w)));
        }
        #pragma unroll
        for (int off = 16; off > 0; off >>= 1)
            mx = fmaxf(mx, __shfl_xor_sync(0xffffffffu, mx, off));

        float sum = 0.f;
        #pragma unroll
        for (int j = 0; j < 8; ++j) {
            p[j].x = __expf(p[j].x - mx);
            p[j].y = __expf(p[j].y - mx);
            p[j].z = __expf(p[j].z - mx);
            p[j].w = __expf(p[j].w - mx);
            sum += (p[j].x + p[j].y) + (p[j].z + p[j].w);
        }
        #pragma unroll
        for (int off = 16; off > 0; off >>= 1)
            sum += __shfl_xor_sync(0xffffffffu, sum, off);
        const float inv = 1.0f / sum;

        const size_t rowbase = ((size_t)b * TSEQ + (q0 + r)) * TSEQ;
        #pragma unroll
        for (int j = 0; j < 8; ++j) {
            const size_t off4 = rowbase + (size_t)(lane + 32 * j) * 4;
            float4 qv = *(const float4*)(qmask + off4);
            float4 o;
            o.x = p[j].x * qv.x * inv;
            o.y = p[j].y * qv.y * inv;
            o.z = p[j].z * qv.z * inv;
            o.w = p[j].w * qv.w * inv;
            *(float4*)(attn_out + off4) = o;
        }
    }
}

// ---------------------------------------------------------------------------
// Kernel 2: result = attn @ V
// Block: 256 threads, 64x64 output tile per (batch, q-tile).
// ---------------------------------------------------------------------------
__global__ __launch_bounds__(256, 2)
void av_kernel(const float* __restrict__ V,
               const float* __restrict__ attn,
               float* __restrict__ out)
{
    __shared__ float sA[64 * 64];
    __shared__ float sV[64 * 64];

    const int b   = blockIdx.y;
    const int q0  = blockIdx.x * 64;
    const int tid = threadIdx.x;
    const int rg  = tid >> 4;     // 16 row groups (4 rows)
    const int cg  = tid & 15;     // 16 col groups (4 cols)
    const int qr  = rg * 4;
    const int dc  = cg * 4;

    float acc[4][4] = {};

    for (int kt = 0; kt < TSEQ / 64; ++kt) {
        const int k0 = kt * 64;
        // load attn tile [64 q][64 k]
        #pragma unroll
        for (int i = 0; i < 4; ++i) {
            int e  = tid + 256 * i;     // float4 idx
            int qq = e >> 4;
            int k4 = (e & 15) * 4;
            *(float4*)(sA + qq * 64 + k4) =
                *(const float4*)(attn + ((size_t)b * TSEQ + q0 + qq) * TSEQ + k0 + k4);
        }
        // load V tile [64 k][64 d]
        #pragma unroll
        for (int i = 0; i < 4; ++i) {
            int e  = tid + 256 * i;
            int kk = e >> 4;
            int d4 = (e & 15) * 4;
            *(float4*)(sV + kk * 64 + d4) =
                *(const float4*)(V + ((size_t)b * TSEQ + k0 + kk) * DK + d4);
        }
        __syncthreads();

        #pragma unroll 8
        for (int k = 0; k < 64; ++k) {
            float a0 = sA[(qr + 0) * 64 + k];
            float a1 = sA[(qr + 1) * 64 + k];
            float a2 = sA[(qr + 2) * 64 + k];
            float a3 = sA[(qr + 3) * 64 + k];
            float4 vv = *(const float4*)(sV + k * 64 + dc);
            acc[0][0] += a0 * vv.x; acc[0][1] += a0 * vv.y; acc[0][2] += a0 * vv.z; acc[0][3] += a0 * vv.w;
            acc[1][0] += a1 * vv.x; acc[1][1] += a1 * vv.y; acc[1][2] += a1 * vv.z; acc[1][3] += a1 * vv.w;
            acc[2][0] += a2 * vv.x; acc[2][1] += a2 * vv.y; acc[2][2] += a2 * vv.z; acc[2][3] += a2 * vv.w;
            acc[3][0] += a3 * vv.x; acc[3][1] += a3 * vv.y; acc[3][2] += a3 * vv.z; acc[3][3] += a3 * vv.w;
        }
        __syncthreads();
    }

    #pragma unroll
    for (int j = 0; j < 4; ++j) {
        float4 o = make_float4(acc[j][0], acc[j][1], acc[j][2], acc[j][3]);
        *(float4*)(out + ((size_t)b * TSEQ + q0 + qr + j) * DK + dc) = o;
    }
}

// ---------------------------------------------------------------------------
extern "C" void kernel_launch(void* const* d_in, const int* in_sizes, int n_in,
                              void* d_out, int out_size)
{
    const float* key   = (const float*)d_in[0];
    const float* value = (const float*)d_in[1];
    const float* query = (const float*)d_in[2];
    const int*   mask  = (const int*)d_in[3];     // bool -> int32
    const float* qmask = (const float*)d_in[4];
    const float* gf    = (const float*)d_in[5];

    float* result = (float*)d_out;                                  // [64,1024,64]
    float* attn   = result + (size_t)BATCH * TSEQ * DK;             // [64,1024,1024]

    const int smem1 = SMEM1_FLOATS * (int)sizeof(float);
    cudaFuncSetAttribute(attn_softmax_kernel,
                         cudaFuncAttributeMaxDynamicSharedMemorySize, smem1);

    dim3 grid1(TSEQ / K1_ROWS, BATCH);
    attn_softmax_kernel<<<grid1, 256, smem1>>>(key, query, mask, qmask, gf, attn);

    dim3 grid2(TSEQ / 64, BATCH);
    av_kernel<<<grid2, 256>>>(value, attn, result);
}

// round 3
// speedup vs baseline: 1.0957x; 1.0957x over previous
#include <cuda_runtime.h>
#include <cstdint>

#define BATCH 64
#define TSEQ  1024
#define DK    64
#define MASK_FILL (-4294967295.0f)   // -2^32 + 1

// ---------------------------------------------------------------------------
// Kernel 1: logits = QK^T/8 - gf, masked fill, softmax, * query_mask -> attn
// Block: 256 threads, 32 query rows of one batch, k-tiles of 128.
// ---------------------------------------------------------------------------
#define K1_ROWS 32
#define K1_KT   128
#define KT_PITCH 132   // sKt row pitch (floats): 128 + 4 pad, 16B-aligned
#define SQ_PITCH 68    // sQ row pitch: 64 + 4 pad
#define SMEM1_FLOATS (K1_ROWS*TSEQ + DK*KT_PITCH + K1_ROWS*SQ_PITCH)

__global__ __launch_bounds__(256, 1)
void attn_softmax_kernel(const float* __restrict__ K,
                         const float* __restrict__ Q,
                         const int*   __restrict__ mask,     // bool as int32
                         const float* __restrict__ qmask,
                         const float* __restrict__ gf,
                         float* __restrict__ attn_out)
{
    extern __shared__ float smem[];
    float* sLog = smem;                          // 32*1024
    float* sKt  = sLog + K1_ROWS * TSEQ;         // 64 x 132 (transposed K tile)
    float* sQ   = sKt + DK * KT_PITCH;           // 32 x 68

    const int b   = blockIdx.y;
    const int q0  = blockIdx.x * K1_ROWS;
    const int tid = threadIdx.x;

    // load Q tile [32][64] -> sQ (pitch 68), coalesced float4
    {
        const float* Qb = Q + ((size_t)b * TSEQ + q0) * DK;
        #pragma unroll
        for (int it = 0; it < 2; ++it) {
            int e  = tid + 256 * it;     // 0..511 float4 slots
            int q  = e >> 4;             // 0..31
            int d4 = (e & 15) * 4;
            float4 v = *(const float4*)(Qb + q * DK + d4);
            *(float4*)(sQ + q * SQ_PITCH + d4) = v;
        }
    }

    const int rg = tid >> 5;       // 8 row groups (4 rows)
    const int cg = tid & 31;       // 32 col groups (4 cols)
    const int qr = rg * 4;
    const int kc = cg * 4;

    __syncthreads();

    for (int kt = 0; kt < TSEQ / K1_KT; ++kt) {
        const int k0 = kt * K1_KT;
        const float* Kb = K + ((size_t)b * TSEQ + k0) * DK;

        // load K tile [128 keys][64 dims], transpose in registers (4x4 blocks)
        // -> sKt[d][k]. float4 STS, conflict-free (lanes consecutive in k).
        #pragma unroll
        for (int it = 0; it < 2; ++it) {
            int idx = tid + 256 * it;        // 0..511 blocks of 4x4
            int kg  = idx & 31;              // k-group
            int dg  = idx >> 5;              // 0..15 d-group
            int kk  = kg * 4;
            int d4  = dg * 4;
            float4 r0 = *(const float4*)(Kb + (kk + 0) * DK + d4);
            float4 r1 = *(const float4*)(Kb + (kk + 1) * DK + d4);
            float4 r2 = *(const float4*)(Kb + (kk + 2) * DK + d4);
            float4 r3 = *(const float4*)(Kb + (kk + 3) * DK + d4);
            *(float4*)(sKt + (d4 + 0) * KT_PITCH + kk) = make_float4(r0.x, r1.x, r2.x, r3.x);
            *(float4*)(sKt + (d4 + 1) * KT_PITCH + kk) = make_float4(r0.y, r1.y, r2.y, r3.y);
            *(float4*)(sKt + (d4 + 2) * KT_PITCH + kk) = make_float4(r0.z, r1.z, r2.z, r3.z);
            *(float4*)(sKt + (d4 + 3) * KT_PITCH + kk) = make_float4(r0.w, r1.w, r2.w, r3.w);
        }
        __syncthreads();

        float4 acc[4];
        #pragma unroll
        for (int i = 0; i < 4; ++i) acc[i] = make_float4(0.f, 0.f, 0.f, 0.f);

        #pragma unroll
        for (int dd = 0; dd < DK; dd += 4) {
            float4 b0 = *(const float4*)(sKt + (dd + 0) * KT_PITCH + kc);
            float4 b1 = *(const float4*)(sKt + (dd + 1) * KT_PITCH + kc);
            float4 b2 = *(const float4*)(sKt + (dd + 2) * KT_PITCH + kc);
            float4 b3 = *(const float4*)(sKt + (dd + 3) * KT_PITCH + kc);
            #pragma unroll
            for (int i = 0; i < 4; ++i) {
                float4 a = *(const float4*)(sQ + (qr + i) * SQ_PITCH + dd);
                acc[i].x += a.x * b0.x + a.y * b1.x + a.z * b2.x + a.w * b3.x;
                acc[i].y += a.x * b0.y + a.y * b1.y + a.z * b2.y + a.w * b3.y;
                acc[i].z += a.x * b0.z + a.y * b1.z + a.z * b2.z + a.w * b3.z;
                acc[i].w += a.x * b0.w + a.y * b1.w + a.z * b2.w + a.w * b3.w;
            }
        }

        // epilogue: scale, subtract gaussian, mask fill, stash into sLog
        #pragma unroll
        for (int i = 0; i < 4; ++i) {
            const int row = qr + i;
            size_t base = ((size_t)b * TSEQ + (q0 + row)) * TSEQ + k0 + kc;
            float4 g = *(const float4*)(gf + base);
            int4   m = *(const int4*)(mask + base);
            float4 s;
            s.x = m.x ? MASK_FILL : fmaf(acc[i].x, 0.125f, -g.x);
            s.y = m.y ? MASK_FILL : fmaf(acc[i].y, 0.125f, -g.y);
            s.z = m.z ? MASK_FILL : fmaf(acc[i].z, 0.125f, -g.z);
            s.w = m.w ? MASK_FILL : fmaf(acc[i].w, 0.125f, -g.w);
            *(float4*)(sLog + row * TSEQ + k0 + kc) = s;
        }
        __syncthreads();
    }

    // softmax: warp w -> rows 4w..4w+3; each lane owns 8 float4 chunks
    const int w    = tid >> 5;
    const int lane = tid & 31;
    #pragma unroll
    for (int rr = 0; rr < 4; ++rr) {
        const int r = w * 4 + rr;
        float4 p[8];
        float mx = -3.4e38f;
        #pragma unroll
        for (int j = 0; j < 8; ++j) {
            p[j] = *(const float4*)(sLog + r * TSEQ + (lane + 32 * j) * 4);
            mx = fmaxf(mx, fmaxf(fmaxf(p[j].x, p[j].y), fmaxf(p[j].z, p[j].w)));
        }
        #pragma unroll
        for (int off = 16; off > 0; off >>= 1)
            mx = fmaxf(mx, __shfl_xor_sync(0xffffffffu, mx, off));

        float sum = 0.f;
        #pragma unroll
        for (int j = 0; j < 8; ++j) {
            p[j].x = __expf(p[j].x - mx);
            p[j].y = __expf(p[j].y - mx);
            p[j].z = __expf(p[j].z - mx);
            p[j].w = __expf(p[j].w - mx);
            sum += (p[j].x + p[j].y) + (p[j].z + p[j].w);
        }
        #pragma unroll
        for (int off = 16; off > 0; off >>= 1)
            sum += __shfl_xor_sync(0xffffffffu, sum, off);
        const float inv = 1.0f / sum;

        const size_t rowbase = ((size_t)b * TSEQ + (q0 + r)) * TSEQ;
        #pragma unroll
        for (int j = 0; j < 8; ++j) {
            const size_t off4 = rowbase + (size_t)(lane + 32 * j) * 4;
            float4 qv = *(const float4*)(qmask + off4);
            float4 o;
            o.x = p[j].x * qv.x * inv;
            o.y = p[j].y * qv.y * inv;
            o.z = p[j].z * qv.z * inv;
            o.w = p[j].w * qv.w * inv;
            *(float4*)(attn_out + off4) = o;
        }
    }
}

// ---------------------------------------------------------------------------
// Kernel 2: result = attn @ V
// Block: 256 threads, 128q x 64d output tile, k-tiles of 128.
// Thread microtile: 8 rows x 4 cols, k-vectorized inner loop (LDS.128 only).
// ---------------------------------------------------------------------------
#define SA_PITCH 132   // 128 + 4 pad
#define SV_PITCH 68    // 64 + 4 pad
#define SMEM2_FLOATS (128*SA_PITCH + 128*SV_PITCH)

__global__ __launch_bounds__(256, 1)
void av_kernel(const float* __restrict__ V,
               const float* __restrict__ attn,
               float* __restrict__ out)
{
    extern __shared__ float smem2[];
    float* sA = smem2;                 // [128 q][132]
    float* sV = sA + 128 * SA_PITCH;   // [128 k][68]

    const int b   = blockIdx.y;
    const int q0  = blockIdx.x * 128;
    const int tid = threadIdx.x;
    const int rg  = tid >> 4;      // 16 row groups (8 rows)
    const int cg  = tid & 15;      // 16 col groups (4 cols)
    const int qr  = rg * 8;
    const int dc  = cg * 4;

    float4 acc[8];
    #pragma unroll
    for (int i = 0; i < 8; ++i) acc[i] = make_float4(0.f, 0.f, 0.f, 0.f);

    for (int kt = 0; kt < TSEQ / 128; ++kt) {
        const int k0 = kt * 128;

        // load attn tile [128 q][128 k], coalesced float4
        #pragma unroll
        for (int i = 0; i < 16; ++i) {
            int e   = tid + 256 * i;      // 0..4095 float4
            int q   = e >> 5;
            int kq4 = (e & 31) * 4;
            *(float4*)(sA + q * SA_PITCH + kq4) =
                *(const float4*)(attn + ((size_t)b * TSEQ + q0 + q) * TSEQ + k0 + kq4);
        }
        // load V tile [128 k][64 d]
        #pragma unroll
        for (int i = 0; i < 8; ++i) {
            int e   = tid + 256 * i;      // 0..2047 float4
            int kk  = e >> 4;
            int dd4 = (e & 15) * 4;
            *(float4*)(sV + kk * SV_PITCH + dd4) =
                *(const float4*)(V + ((size_t)b * TSEQ + k0 + kk) * DK + dd4);
        }
        __syncthreads();

        #pragma unroll 2
        for (int k4 = 0; k4 < 32; ++k4) {
            const int k = k4 * 4;
            float4 b0 = *(const float4*)(sV + (k + 0) * SV_PITCH + dc);
            float4 b1 = *(const float4*)(sV + (k + 1) * SV_PITCH + dc);
            float4 b2 = *(const float4*)(sV + (k + 2) * SV_PITCH + dc);
            float4 b3 = *(const float4*)(sV + (k + 3) * SV_PITCH + dc);
            #pragma unroll
            for (int i = 0; i < 8; ++i) {
                float4 a = *(const float4*)(sA + (qr + i) * SA_PITCH + k);
                acc[i].x += a.x * b0.x + a.y * b1.x + a.z * b2.x + a.w * b3.x;
                acc[i].y += a.x * b0.y + a.y * b1.y + a.z * b2.y + a.w * b3.y;
                acc[i].z += a.x * b0.z + a.y * b1.z + a.z * b2.z + a.w * b3.z;
                acc[i].w += a.x * b0.w + a.y * b1.w + a.z * b2.w + a.w * b3.w;
            }
        }
        __syncthreads();
    }

    #pragma unroll
    for (int i = 0; i < 8; ++i) {
        *(float4*)(out + ((size_t)b * TSEQ + q0 + qr + i) * DK + dc) = acc[i];
    }
}

// ---------------------------------------------------------------------------
extern "C" void kernel_launch(void* const* d_in, const int* in_sizes, int n_in,
                              void* d_out, int out_size)
{
    const float* key   = (const float*)d_in[0];
    const float* value = (const float*)d_in[1];
    const float* query = (const float*)d_in[2];
    const int*   mask  = (const int*)d_in[3];     // bool -> int32
    const float* qmask = (const float*)d_in[4];
    const float* gf    = (const float*)d_in[5];

    float* result = (float*)d_out;                                  // [64,1024,64]
    float* attn   = result + (size_t)BATCH * TSEQ * DK;             // [64,1024,1024]

    const int smem1 = SMEM1_FLOATS * (int)sizeof(float);
    cudaFuncSetAttribute(attn_softmax_kernel,
                         cudaFuncAttributeMaxDynamicSharedMemorySize, smem1);
    const int smem2 = SMEM2_FLOATS * (int)sizeof(float);
    cudaFuncSetAttribute(av_kernel,
                         cudaFuncAttributeMaxDynamicSharedMemorySize, smem2);

    dim3 grid1(TSEQ / K1_ROWS, BATCH);
    attn_softmax_kernel<<<grid1, 256, smem1>>>(key, query, mask, qmask, gf, attn);

    dim3 grid2(TSEQ / 128, BATCH);
    av_kernel<<<grid2, 256, smem2>>>(value, attn, result);
}

// round 4
// speedup vs baseline: 1.1162x; 1.0187x over previous
#include <cuda_runtime.h>
#include <cstdint>

#define BATCH 64
#define TSEQ  1024
#define DK    64
#define MASK_FILL (-4294967295.0f)   // -2^32 + 1

// ---------------- packed f32x2 helpers (Blackwell FFMA2 path) --------------
__device__ __forceinline__ unsigned long long pack2(float v) {
    unsigned long long r;
    unsigned u = __float_as_uint(v);
    asm("mov.b64 %0, {%1, %1};" : "=l"(r) : "r"(u));
    return r;
}
__device__ __forceinline__ void ffma2(unsigned long long& d,
                                      unsigned long long a,
                                      unsigned long long b) {
    asm("fma.rn.f32x2 %0, %1, %2, %3;" : "=l"(d) : "l"(a), "l"(b), "l"(d));
}
__device__ __forceinline__ float2 unpack2(unsigned long long p) {
    unsigned lo, hi;
    asm("mov.b64 {%0, %1}, %2;" : "=r"(lo), "=r"(hi) : "l"(p));
    return make_float2(__uint_as_float(lo), __uint_as_float(hi));
}

// ---------------------------------------------------------------------------
// Kernel 1: logits = QK^T/8 - gf, masked fill, softmax, * query_mask -> attn
// Block: 256 threads, 32 query rows of one batch, k-tiles of 128.
// Thread microtile 4q x 4k; accumulators packed over q-pairs (FFMA2).
// ---------------------------------------------------------------------------
#define K1_ROWS 32
#define K1_KT   128
#define KT_PITCH 132   // sKt row pitch (floats)
#define SQT_PITCH 36   // sQt row pitch (floats): 32 + 4 pad (16B multiple)
#define SMEM1_FLOATS (K1_ROWS*TSEQ + DK*KT_PITCH + DK*SQT_PITCH)

__global__ __launch_bounds__(256, 1)
void attn_softmax_kernel(const float* __restrict__ K,
                         const float* __restrict__ Q,
                         const int*   __restrict__ mask,     // bool as int32
                         const float* __restrict__ qmask,
                         const float* __restrict__ gf,
                         float* __restrict__ attn_out)
{
    extern __shared__ float smem[];
    float* sLog = smem;                          // 32*1024
    float* sKt  = sLog + K1_ROWS * TSEQ;         // [64 d][132] transposed K tile
    float* sQt  = sKt + DK * KT_PITCH;           // [64 d][36]  transposed Q tile

    const int b   = blockIdx.y;
    const int q0  = blockIdx.x * K1_ROWS;
    const int tid = threadIdx.x;

    // load Q tile [32q][64d] transposed -> sQt[d][q] via 4x4 register blocks
    if (tid < 128) {
        const float* Qb = Q + ((size_t)b * TSEQ + q0) * DK;
        int qg = tid & 7;          // 8 q-groups of 4
        int dg = tid >> 3;         // 16 d-groups of 4
        int qq = qg * 4;
        int d4 = dg * 4;
        float4 r0 = *(const float4*)(Qb + (qq + 0) * DK + d4);
        float4 r1 = *(const float4*)(Qb + (qq + 1) * DK + d4);
        float4 r2 = *(const float4*)(Qb + (qq + 2) * DK + d4);
        float4 r3 = *(const float4*)(Qb + (qq + 3) * DK + d4);
        *(float4*)(sQt + (d4 + 0) * SQT_PITCH + qq) = make_float4(r0.x, r1.x, r2.x, r3.x);
        *(float4*)(sQt + (d4 + 1) * SQT_PITCH + qq) = make_float4(r0.y, r1.y, r2.y, r3.y);
        *(float4*)(sQt + (d4 + 2) * SQT_PITCH + qq) = make_float4(r0.z, r1.z, r2.z, r3.z);
        *(float4*)(sQt + (d4 + 3) * SQT_PITCH + qq) = make_float4(r0.w, r1.w, r2.w, r3.w);
    }

    const int rg = tid >> 5;       // 8 row groups (4 rows)
    const int cg = tid & 31;       // 32 col groups (4 cols)
    const int qr = rg * 4;
    const int kc = cg * 4;

    __syncthreads();

    for (int kt = 0; kt < TSEQ / K1_KT; ++kt) {
        const int k0 = kt * K1_KT;
        const float* Kb = K + ((size_t)b * TSEQ + k0) * DK;

        // load K tile [128 keys][64 dims] transposed -> sKt[d][k]
        #pragma unroll
        for (int it = 0; it < 2; ++it) {
            int idx = tid + 256 * it;        // 0..511 blocks of 4x4
            int kg  = idx & 31;
            int dg  = idx >> 5;              // 0..15
            int kk  = kg * 4;
            int d4  = dg * 4;
            float4 r0 = *(const float4*)(Kb + (kk + 0) * DK + d4);
            float4 r1 = *(const float4*)(Kb + (kk + 1) * DK + d4);
            float4 r2 = *(const float4*)(Kb + (kk + 2) * DK + d4);
            float4 r3 = *(const float4*)(Kb + (kk + 3) * DK + d4);
            *(float4*)(sKt + (d4 + 0) * KT_PITCH + kk) = make_float4(r0.x, r1.x, r2.x, r3.x);
            *(float4*)(sKt + (d4 + 1) * KT_PITCH + kk) = make_float4(r0.y, r1.y, r2.y, r3.y);
            *(float4*)(sKt + (d4 + 2) * KT_PITCH + kk) = make_float4(r0.z, r1.z, r2.z, r3.z);
            *(float4*)(sKt + (d4 + 3) * KT_PITCH + kk) = make_float4(r0.w, r1.w, r2.w, r3.w);
        }
        __syncthreads();

        unsigned long long acc[2][4];
        #pragma unroll
        for (int p = 0; p < 2; ++p)
            #pragma unroll
            for (int c = 0; c < 4; ++c) acc[p][c] = 0ull;

        #pragma unroll 16
        for (int d = 0; d < DK; ++d) {
            ulonglong2 ap = *(const ulonglong2*)(sQt + d * SQT_PITCH + qr); // 2 q-pairs
            float4 bv = *(const float4*)(sKt + d * KT_PITCH + kc);
            unsigned long long b0 = pack2(bv.x);
            unsigned long long b1 = pack2(bv.y);
            unsigned long long b2 = pack2(bv.z);
            unsigned long long b3 = pack2(bv.w);
            ffma2(acc[0][0], ap.x, b0); ffma2(acc[0][1], ap.x, b1);
            ffma2(acc[0][2], ap.x, b2); ffma2(acc[0][3], ap.x, b3);
            ffma2(acc[1][0], ap.y, b0); ffma2(acc[1][1], ap.y, b1);
            ffma2(acc[1][2], ap.y, b2); ffma2(acc[1][3], ap.y, b3);
        }

        // epilogue: scale, subtract gaussian, mask fill, stash into sLog
        #pragma unroll
        for (int p = 0; p < 2; ++p) {
            float2 v0 = unpack2(acc[p][0]);
            float2 v1 = unpack2(acc[p][1]);
            float2 v2 = unpack2(acc[p][2]);
            float2 v3 = unpack2(acc[p][3]);
            #pragma unroll
            for (int h = 0; h < 2; ++h) {
                const int row = qr + p * 2 + h;
                float a0 = h ? v0.y : v0.x;
                float a1 = h ? v1.y : v1.x;
                float a2 = h ? v2.y : v2.x;
                float a3 = h ? v3.y : v3.x;
                size_t base = ((size_t)b * TSEQ + (q0 + row)) * TSEQ + k0 + kc;
                float4 g = *(const float4*)(gf + base);
                int4   m = *(const int4*)(mask + base);
                float4 s;
                s.x = m.x ? MASK_FILL : fmaf(a0, 0.125f, -g.x);
                s.y = m.y ? MASK_FILL : fmaf(a1, 0.125f, -g.y);
                s.z = m.z ? MASK_FILL : fmaf(a2, 0.125f, -g.z);
                s.w = m.w ? MASK_FILL : fmaf(a3, 0.125f, -g.w);
                *(float4*)(sLog + row * TSEQ + k0 + kc) = s;
            }
        }
        __syncthreads();
    }

    // softmax: warp w -> rows 4w..4w+3; each lane owns 8 float4 chunks
    const int w    = tid >> 5;
    const int lane = tid & 31;
    #pragma unroll
    for (int rr = 0; rr < 4; ++rr) {
        const int r = w * 4 + rr;
        float4 p[8];
        float mx = -3.4e38f;
        #pragma unroll
        for (int j = 0; j < 8; ++j) {
            p[j] = *(const float4*)(sLog + r * TSEQ + (lane + 32 * j) * 4);
            mx = fmaxf(mx, fmaxf(fmaxf(p[j].x, p[j].y), fmaxf(p[j].z, p[j].w)));
        }
        #pragma unroll
        for (int off = 16; off > 0; off >>= 1)
            mx = fmaxf(mx, __shfl_xor_sync(0xffffffffu, mx, off));

        float sum = 0.f;
        #pragma unroll
        for (int j = 0; j < 8; ++j) {
            p[j].x = __expf(p[j].x - mx);
            p[j].y = __expf(p[j].y - mx);
            p[j].z = __expf(p[j].z - mx);
            p[j].w = __expf(p[j].w - mx);
            sum += (p[j].x + p[j].y) + (p[j].z + p[j].w);
        }
        #pragma unroll
        for (int off = 16; off > 0; off >>= 1)
            sum += __shfl_xor_sync(0xffffffffu, sum, off);
        const float inv = 1.0f / sum;

        const size_t rowbase = ((size_t)b * TSEQ + (q0 + r)) * TSEQ;
        #pragma unroll
        for (int j = 0; j < 8; ++j) {
            const size_t off4 = rowbase + (size_t)(lane + 32 * j) * 4;
            float4 qv = *(const float4*)(qmask + off4);
            float4 o;
            o.x = p[j].x * qv.x * inv;
            o.y = p[j].y * qv.y * inv;
            o.z = p[j].z * qv.z * inv;
            o.w = p[j].w * qv.w * inv;
            *(float4*)(attn_out + off4) = o;
        }
    }
}

// ---------------------------------------------------------------------------
// Kernel 2: result = attn @ V
// Block: 256 threads, 128q x 64d output tile, k-chunks of 64.
// Thread microtile 8q x 4d; q-pair packed accumulators (FFMA2).
// attn chunk stored transposed: sAt[k][q].
// ---------------------------------------------------------------------------
#define SAT_PITCH 132   // 128 q + 4 pad
#define SV_PITCH  68    // 64 d + 4 pad
#define K2_KC     64
#define SMEM2_FLOATS (K2_KC*SAT_PITCH + K2_KC*SV_PITCH)

__global__ __launch_bounds__(256, 2)
void av_kernel(const float* __restrict__ V,
               const float* __restrict__ attn,
               float* __restrict__ out)
{
    extern __shared__ float smem2[];
    float* sAt = smem2;                    // [64 k][132 q]
    float* sV  = sAt + K2_KC * SAT_PITCH;  // [64 k][68 d]

    const int b   = blockIdx.y;
    const int q0  = blockIdx.x * 128;
    const int tid = threadIdx.x;
    const int rg  = tid >> 4;      // 16 row groups (8 rows)
    const int cg  = tid & 15;      // 16 col groups (4 cols)
    const int qr  = rg * 8;
    const int dc  = cg * 4;

    unsigned long long acc[4][4];
    #pragma unroll
    for (int p = 0; p < 4; ++p)
        #pragma unroll
        for (int c = 0; c < 4; ++c) acc[p][c] = 0ull;

    for (int kt = 0; kt < TSEQ / K2_KC; ++kt) {
        const int k0 = kt * K2_KC;

        // attn tile [128 q][64 k] -> transposed sAt[k][q] via 4x4 blocks
        #pragma unroll
        for (int it = 0; it < 2; ++it) {
            int e  = tid + 256 * it;   // 0..511 blocks
            int kg = e & 15;           // 16 k-groups
            int qg = e >> 4;           // 32 q-groups
            int kk = kg * 4;
            int qq = qg * 4;
            const float* Ab = attn + ((size_t)b * TSEQ + q0 + qq) * TSEQ + k0 + kk;
            float4 r0 = *(const float4*)(Ab + 0 * TSEQ);
            float4 r1 = *(const float4*)(Ab + 1 * TSEQ);
            float4 r2 = *(const float4*)(Ab + 2 * TSEQ);
            float4 r3 = *(const float4*)(Ab + 3 * TSEQ);
            *(float4*)(sAt + (kk + 0) * SAT_PITCH + qq) = make_float4(r0.x, r1.x, r2.x, r3.x);
            *(float4*)(sAt + (kk + 1) * SAT_PITCH + qq) = make_float4(r0.y, r1.y, r2.y, r3.y);
            *(float4*)(sAt + (kk + 2) * SAT_PITCH + qq) = make_float4(r0.z, r1.z, r2.z, r3.z);
            *(float4*)(sAt + (kk + 3) * SAT_PITCH + qq) = make_float4(r0.w, r1.w, r2.w, r3.w);
        }
        // V tile [64 k][64 d]
        #pragma unroll
        for (int i = 0; i < 4; ++i) {
            int e   = tid + 256 * i;      // 0..1023 float4
            int kk  = e >> 4;
            int dd4 = (e & 15) * 4;
            *(float4*)(sV + kk * SV_PITCH + dd4) =
                *(const float4*)(V + ((size_t)b * TSEQ + k0 + kk) * DK + dd4);
        }
        __syncthreads();

        #pragma unroll 8
        for (int k = 0; k < K2_KC; ++k) {
            ulonglong2 a01 = *(const ulonglong2*)(sAt + k * SAT_PITCH + qr);     // q pairs 0,1
            ulonglong2 a23 = *(const ulonglong2*)(sAt + k * SAT_PITCH + qr + 4); // q pairs 2,3
            float4 bv = *(const float4*)(sV + k * SV_PITCH + dc);
            unsigned long long b0 = pack2(bv.x);
            unsigned long long b1 = pack2(bv.y);
            unsigned long long b2 = pack2(bv.z);
            unsigned long long b3 = pack2(bv.w);
            ffma2(acc[0][0], a01.x, b0); ffma2(acc[0][1], a01.x, b1);
            ffma2(acc[0][2], a01.x, b2); ffma2(acc[0][3], a01.x, b3);
            ffma2(acc[1][0], a01.y, b0); ffma2(acc[1][1], a01.y, b1);
            ffma2(acc[1][2], a01.y, b2); ffma2(acc[1][3], a01.y, b3);
            ffma2(acc[2][0], a23.x, b0); ffma2(acc[2][1], a23.x, b1);
            ffma2(acc[2][2], a23.x, b2); ffma2(acc[2][3], a23.x, b3);
            ffma2(acc[3][0], a23.y, b0); ffma2(acc[3][1], a23.y, b1);
            ffma2(acc[3][2], a23.y, b2); ffma2(acc[3][3], a23.y, b3);
        }
        __syncthreads();
    }

    #pragma unroll
    for (int p = 0; p < 4; ++p) {
        float2 v0 = unpack2(acc[p][0]);
        float2 v1 = unpack2(acc[p][1]);
        float2 v2 = unpack2(acc[p][2]);
        float2 v3 = unpack2(acc[p][3]);
        float* o0 = out + ((size_t)b * TSEQ + q0 + qr + p * 2 + 0) * DK + dc;
        float* o1 = out + ((size_t)b * TSEQ + q0 + qr + p * 2 + 1) * DK + dc;
        *(float4*)o0 = make_float4(v0.x, v1.x, v2.x, v3.x);
        *(float4*)o1 = make_float4(v0.y, v1.y, v2.y, v3.y);
    }
}

// ---------------------------------------------------------------------------
extern "C" void kernel_launch(void* const* d_in, const int* in_sizes, int n_in,
                              void* d_out, int out_size)
{
    const float* key   = (const float*)d_in[0];
    const float* value = (const float*)d_in[1];
    const float* query = (const float*)d_in[2];
    const int*   mask  = (const int*)d_in[3];     // bool -> int32
    const float* qmask = (const float*)d_in[4];
    const float* gf    = (const float*)d_in[5];

    float* result = (float*)d_out;                                  // [64,1024,64]
    float* attn   = result + (size_t)BATCH * TSEQ * DK;             // [64,1024,1024]

    const int smem1 = SMEM1_FLOATS * (int)sizeof(float);
    cudaFuncSetAttribute(attn_softmax_kernel,
                         cudaFuncAttributeMaxDynamicSharedMemorySize, smem1);
    const int smem2 = SMEM2_FLOATS * (int)sizeof(float);
    cudaFuncSetAttribute(av_kernel,
                         cudaFuncAttributeMaxDynamicSharedMemorySize, smem2);

    dim3 grid1(TSEQ / K1_ROWS, BATCH);
    attn_softmax_kernel<<<grid1, 256, smem1>>>(key, query, mask, qmask, gf, attn);

    dim3 grid2(TSEQ / 128, BATCH);
    av_kernel<<<grid2, 256, smem2>>>(value, attn, result);
}

// round 5
// speedup vs baseline: 1.2129x; 1.0866x over previous
#include <cuda_runtime.h>
#include <cstdint>

#define BATCH 64
#define TSEQ  1024
#define DK    64
#define MASK_FILL (-4294967295.0f)   // -2^32 + 1

// ---------------- packed f32x2 helpers (Blackwell FFMA2 path) --------------
__device__ __forceinline__ unsigned long long pack2(float v) {
    unsigned long long r;
    unsigned u = __float_as_uint(v);
    asm("mov.b64 %0, {%1, %1};" : "=l"(r) : "r"(u));
    return r;
}
__device__ __forceinline__ void ffma2(unsigned long long& d,
                                      unsigned long long a,
                                      unsigned long long b) {
    asm("fma.rn.f32x2 %0, %1, %2, %3;" : "=l"(d) : "l"(a), "l"(b), "l"(d));
}
__device__ __forceinline__ float2 unpack2(unsigned long long p) {
    unsigned lo, hi;
    asm("mov.b64 {%0, %1}, %2;" : "=r"(lo), "=r"(hi) : "l"(p));
    return make_float2(__uint_as_float(lo), __uint_as_float(hi));
}

// ---------------------------------------------------------------------------
// Kernel 1: logits = QK^T/8 - gf, masked fill, softmax, * query_mask -> attn
// Block: 512 threads, 32 q-rows, k-tiles of 128; ALL logits live in registers
// (64 floats/thread). Softmax via warp shuffles + tiny 2-warp smem combine.
// ---------------------------------------------------------------------------
#define K1_Q   32
#define K1_KT  128
#define NKT    (TSEQ / K1_KT)     // 8
#define KT_PITCH 132              // sKt row pitch (floats)
#define SQT_PITCH 36              // sQt row pitch (floats)
#define SMEM1_FLOATS (DK*KT_PITCH + DK*SQT_PITCH + 2*8*4*2)

__global__ __launch_bounds__(512, 1)
void attn_softmax_kernel(const float* __restrict__ K,
                         const float* __restrict__ Q,
                         const int*   __restrict__ mask,     // bool as int32
                         const float* __restrict__ qmask,
                         const float* __restrict__ gf,
                         float* __restrict__ attn_out)
{
    extern __shared__ float smem[];
    float* sKt   = smem;                      // [64 d][132] transposed K tile
    float* sQt   = sKt + DK * KT_PITCH;       // [64 d][36]  transposed Q tile
    float* sRedM = sQt + DK * SQT_PITCH;      // [8 rg][4 row][2 warp]
    float* sRedS = sRedM + 8 * 4 * 2;         // [8 rg][4 row][2 warp]

    const int b   = blockIdx.y;
    const int q0  = blockIdx.x * K1_Q;
    const int tid = threadIdx.x;

    const int rg = tid >> 6;         // 8 row groups (4 rows each)
    const int cg = tid & 63;         // 64 col groups (2 cols each)
    const int qr = rg * 4;
    const int kc = cg * 2;
    const int lane = tid & 31;
    const int wp   = (tid >> 5) & 1; // warp parity inside row group

    const float* Kbase = K + (size_t)b * TSEQ * DK;

    // Q tile [32q][64d] transposed -> sQt[d][q] via 4x4 register blocks
    if (tid < 128) {
        const float* Qb = Q + ((size_t)b * TSEQ + q0) * DK;
        int qg = tid & 7;
        int dg = tid >> 3;
        int qq = qg * 4;
        int d4 = dg * 4;
        float4 r0 = *(const float4*)(Qb + (qq + 0) * DK + d4);
        float4 r1 = *(const float4*)(Qb + (qq + 1) * DK + d4);
        float4 r2 = *(const float4*)(Qb + (qq + 2) * DK + d4);
        float4 r3 = *(const float4*)(Qb + (qq + 3) * DK + d4);
        *(float4*)(sQt + (d4 + 0) * SQT_PITCH + qq) = make_float4(r0.x, r1.x, r2.x, r3.x);
        *(float4*)(sQt + (d4 + 1) * SQT_PITCH + qq) = make_float4(r0.y, r1.y, r2.y, r3.y);
        *(float4*)(sQt + (d4 + 2) * SQT_PITCH + qq) = make_float4(r0.z, r1.z, r2.z, r3.z);
        *(float4*)(sQt + (d4 + 3) * SQT_PITCH + qq) = make_float4(r0.w, r1.w, r2.w, r3.w);
    }

    // K-tile transpose assignment: 1 4x4 block per thread
    const int kg  = tid & 31;        // 32 k-groups of 4
    const int dgK = tid >> 5;        // 16 d-groups of 4
    const int kkK = kg * 4;
    const int d4K = dgK * 4;

    // preload K tile for kt=0
    float4 rk0, rk1, rk2, rk3;
    {
        const float* Kb = Kbase;
        rk0 = *(const float4*)(Kb + (kkK + 0) * DK + d4K);
        rk1 = *(const float4*)(Kb + (kkK + 1) * DK + d4K);
        rk2 = *(const float4*)(Kb + (kkK + 2) * DK + d4K);
        rk3 = *(const float4*)(Kb + (kkK + 3) * DK + d4K);
    }

    float lg[NKT][4][2];             // all logits in registers

    #pragma unroll
    for (int kt = 0; kt < NKT; ++kt) {
        // store prefetched K tile (transposed) into sKt
        *(float4*)(sKt + (d4K + 0) * KT_PITCH + kkK) = make_float4(rk0.x, rk1.x, rk2.x, rk3.x);
        *(float4*)(sKt + (d4K + 1) * KT_PITCH + kkK) = make_float4(rk0.y, rk1.y, rk2.y, rk3.y);
        *(float4*)(sKt + (d4K + 2) * KT_PITCH + kkK) = make_float4(rk0.z, rk1.z, rk2.z, rk3.z);
        *(float4*)(sKt + (d4K + 3) * KT_PITCH + kkK) = make_float4(rk0.w, rk1.w, rk2.w, rk3.w);
        __syncthreads();

        // prefetch next K tile
        if (kt < NKT - 1) {
            const float* Kb = Kbase + (size_t)(kt + 1) * K1_KT * DK;
            rk0 = *(const float4*)(Kb + (kkK + 0) * DK + d4K);
            rk1 = *(const float4*)(Kb + (kkK + 1) * DK + d4K);
            rk2 = *(const float4*)(Kb + (kkK + 2) * DK + d4K);
            rk3 = *(const float4*)(Kb + (kkK + 3) * DK + d4K);
        }

        // prefetch gf/mask for this tile's epilogue (hidden behind GEMM)
        float2 gv[4]; int2 mv[4];
        #pragma unroll
        for (int i = 0; i < 4; ++i) {
            size_t base = ((size_t)b * TSEQ + (q0 + qr + i)) * TSEQ + kt * K1_KT + kc;
            gv[i] = *(const float2*)(gf + base);
            mv[i] = *(const int2*)(mask + base);
        }

        // GEMM: 4q x 2k microtile, FFMA2 over q-pairs
        unsigned long long acc00 = 0ull, acc01 = 0ull, acc10 = 0ull, acc11 = 0ull;
        #pragma unroll 16
        for (int d = 0; d < DK; ++d) {
            ulonglong2 ap = *(const ulonglong2*)(sQt + d * SQT_PITCH + qr);
            float2 bv = *(const float2*)(sKt + d * KT_PITCH + kc);
            unsigned long long b0 = pack2(bv.x);
            unsigned long long b1 = pack2(bv.y);
            ffma2(acc00, ap.x, b0); ffma2(acc01, ap.x, b1);
            ffma2(acc10, ap.y, b0); ffma2(acc11, ap.y, b1);
        }

        // epilogue into logit registers
        {
            float2 v00 = unpack2(acc00);   // rows qr+0, qr+1 @ kc
            float2 v01 = unpack2(acc01);   // rows qr+0, qr+1 @ kc+1
            float2 v10 = unpack2(acc10);   // rows qr+2, qr+3 @ kc
            float2 v11 = unpack2(acc11);   // rows qr+2, qr+3 @ kc+1
            lg[kt][0][0] = mv[0].x ? MASK_FILL : fmaf(v00.x, 0.125f, -gv[0].x);
            lg[kt][0][1] = mv[0].y ? MASK_FILL : fmaf(v01.x, 0.125f, -gv[0].y);
            lg[kt][1][0] = mv[1].x ? MASK_FILL : fmaf(v00.y, 0.125f, -gv[1].x);
            lg[kt][1][1] = mv[1].y ? MASK_FILL : fmaf(v01.y, 0.125f, -gv[1].y);
            lg[kt][2][0] = mv[2].x ? MASK_FILL : fmaf(v10.x, 0.125f, -gv[2].x);
            lg[kt][2][1] = mv[2].y ? MASK_FILL : fmaf(v11.x, 0.125f, -gv[2].y);
            lg[kt][3][0] = mv[3].x ? MASK_FILL : fmaf(v10.y, 0.125f, -gv[3].x);
            lg[kt][3][1] = mv[3].y ? MASK_FILL : fmaf(v11.y, 0.125f, -gv[3].y);
        }
        __syncthreads();   // protect sKt before next tile's STS
    }

    // ---------------- softmax over register-held logits ----------------
    // row r (of this block's 32) is owned by exactly 2 warps (row group rg).
    float pmax[4];
    #pragma unroll
    for (int i = 0; i < 4; ++i) {
        float m = -3.4e38f;
        #pragma unroll
        for (int kt = 0; kt < NKT; ++kt) {
            m = fmaxf(m, fmaxf(lg[kt][i][0], lg[kt][i][1]));
        }
        #pragma unroll
        for (int off = 16; off > 0; off >>= 1)
            m = fmaxf(m, __shfl_xor_sync(0xffffffffu, m, off));
        pmax[i] = m;
    }
    if (lane == 0) {
        #pragma unroll
        for (int i = 0; i < 4; ++i) sRedM[(rg * 4 + i) * 2 + wp] = pmax[i];
    }
    __syncthreads();

    float rmax[4];
    #pragma unroll
    for (int i = 0; i < 4; ++i)
        rmax[i] = fmaxf(sRedM[(rg * 4 + i) * 2 + 0], sRedM[(rg * 4 + i) * 2 + 1]);

    float psum[4];
    #pragma unroll
    for (int i = 0; i < 4; ++i) {
        float s = 0.f;
        #pragma unroll
        for (int kt = 0; kt < NKT; ++kt) {
            lg[kt][i][0] = __expf(lg[kt][i][0] - rmax[i]);
            lg[kt][i][1] = __expf(lg[kt][i][1] - rmax[i]);
            s += lg[kt][i][0] + lg[kt][i][1];
        }
        #pragma unroll
        for (int off = 16; off > 0; off >>= 1)
            s += __shfl_xor_sync(0xffffffffu, s, off);
        psum[i] = s;
    }
    if (lane == 0) {
        #pragma unroll
        for (int i = 0; i < 4; ++i) sRedS[(rg * 4 + i) * 2 + wp] = psum[i];
    }
    __syncthreads();

    float inv[4];
    #pragma unroll
    for (int i = 0; i < 4; ++i)
        inv[i] = 1.0f / (sRedS[(rg * 4 + i) * 2 + 0] + sRedS[(rg * 4 + i) * 2 + 1]);

    // normalize, * query_mask, write attn (coalesced 256B/warp segments)
    #pragma unroll
    for (int i = 0; i < 4; ++i) {
        const size_t rowbase = ((size_t)b * TSEQ + (q0 + qr + i)) * TSEQ + kc;
        #pragma unroll
        for (int kt = 0; kt < NKT; ++kt) {
            const size_t off2 = rowbase + (size_t)kt * K1_KT;
            float2 qv = *(const float2*)(qmask + off2);
            float2 o;
            o.x = lg[kt][i][0] * qv.x * inv[i];
            o.y = lg[kt][i][1] * qv.y * inv[i];
            *(float2*)(attn_out + off2) = o;
        }
    }
}

// ---------------------------------------------------------------------------
// Kernel 2: result = attn @ V  (unchanged from round 4)
// ---------------------------------------------------------------------------
#define SAT_PITCH 132   // 128 q + 4 pad
#define SV_PITCH  68    // 64 d + 4 pad
#define K2_KC     64
#define SMEM2_FLOATS (K2_KC*SAT_PITCH + K2_KC*SV_PITCH)

__global__ __launch_bounds__(256, 2)
void av_kernel(const float* __restrict__ V,
               const float* __restrict__ attn,
               float* __restrict__ out)
{
    extern __shared__ float smem2[];
    float* sAt = smem2;                    // [64 k][132 q]
    float* sV  = sAt + K2_KC * SAT_PITCH;  // [64 k][68 d]

    const int b   = blockIdx.y;
    const int q0  = blockIdx.x * 128;
    const int tid = threadIdx.x;
    const int rg  = tid >> 4;
    const int cg  = tid & 15;
    const int qr  = rg * 8;
    const int dc  = cg * 4;

    unsigned long long acc[4][4];
    #pragma unroll
    for (int p = 0; p < 4; ++p)
        #pragma unroll
        for (int c = 0; c < 4; ++c) acc[p][c] = 0ull;

    for (int kt = 0; kt < TSEQ / K2_KC; ++kt) {
        const int k0 = kt * K2_KC;

        #pragma unroll
        for (int it = 0; it < 2; ++it) {
            int e  = tid + 256 * it;
            int kg = e & 15;
            int qg = e >> 4;
            int kk = kg * 4;
            int qq = qg * 4;
            const float* Ab = attn + ((size_t)b * TSEQ + q0 + qq) * TSEQ + k0 + kk;
            float4 r0 = *(const float4*)(Ab + 0 * TSEQ);
            float4 r1 = *(const float4*)(Ab + 1 * TSEQ);
            float4 r2 = *(const float4*)(Ab + 2 * TSEQ);
            float4 r3 = *(const float4*)(Ab + 3 * TSEQ);
            *(float4*)(sAt + (kk + 0) * SAT_PITCH + qq) = make_float4(r0.x, r1.x, r2.x, r3.x);
            *(float4*)(sAt + (kk + 1) * SAT_PITCH + qq) = make_float4(r0.y, r1.y, r2.y, r3.y);
            *(float4*)(sAt + (kk + 2) * SAT_PITCH + qq) = make_float4(r0.z, r1.z, r2.z, r3.z);
            *(float4*)(sAt + (kk + 3) * SAT_PITCH + qq) = make_float4(r0.w, r1.w, r2.w, r3.w);
        }
        #pragma unroll
        for (int i = 0; i < 4; ++i) {
            int e   = tid + 256 * i;
            int kk  = e >> 4;
            int dd4 = (e & 15) * 4;
            *(float4*)(sV + kk * SV_PITCH + dd4) =
                *(const float4*)(V + ((size_t)b * TSEQ + k0 + kk) * DK + dd4);
        }
        __syncthreads();

        #pragma unroll 8
        for (int k = 0; k < K2_KC; ++k) {
            ulonglong2 a01 = *(const ulonglong2*)(sAt + k * SAT_PITCH + qr);
            ulonglong2 a23 = *(const ulonglong2*)(sAt + k * SAT_PITCH + qr + 4);
            float4 bv = *(const float4*)(sV + k * SV_PITCH + dc);
            unsigned long long b0 = pack2(bv.x);
            unsigned long long b1 = pack2(bv.y);
            unsigned long long b2 = pack2(bv.z);
            unsigned long long b3 = pack2(bv.w);
            ffma2(acc[0][0], a01.x, b0); ffma2(acc[0][1], a01.x, b1);
            ffma2(acc[0][2], a01.x, b2); ffma2(acc[0][3], a01.x, b3);
            ffma2(acc[1][0], a01.y, b0); ffma2(acc[1][1], a01.y, b1);
            ffma2(acc[1][2], a01.y, b2); ffma2(acc[1][3], a01.y, b3);
            ffma2(acc[2][0], a23.x, b0); ffma2(acc[2][1], a23.x, b1);
            ffma2(acc[2][2], a23.x, b2); ffma2(acc[2][3], a23.x, b3);
            ffma2(acc[3][0], a23.y, b0); ffma2(acc[3][1], a23.y, b1);
            ffma2(acc[3][2], a23.y, b2); ffma2(acc[3][3], a23.y, b3);
        }
        __syncthreads();
    }

    #pragma unroll
    for (int p = 0; p < 4; ++p) {
        float2 v0 = unpack2(acc[p][0]);
        float2 v1 = unpack2(acc[p][1]);
        float2 v2 = unpack2(acc[p][2]);
        float2 v3 = unpack2(acc[p][3]);
        float* o0 = out + ((size_t)b * TSEQ + q0 + qr + p * 2 + 0) * DK + dc;
        float* o1 = out + ((size_t)b * TSEQ + q0 + qr + p * 2 + 1) * DK + dc;
        *(float4*)o0 = make_float4(v0.x, v1.x, v2.x, v3.x);
        *(float4*)o1 = make_float4(v0.y, v1.y, v2.y, v3.y);
    }
}

// ---------------------------------------------------------------------------
extern "C" void kernel_launch(void* const* d_in, const int* in_sizes, int n_in,
                              void* d_out, int out_size)
{
    const float* key   = (const float*)d_in[0];
    const float* value = (const float*)d_in[1];
    const float* query = (const float*)d_in[2];
    const int*   mask  = (const int*)d_in[3];     // bool -> int32
    const float* qmask = (const float*)d_in[4];
    const float* gf    = (const float*)d_in[5];

    float* result = (float*)d_out;                                  // [64,1024,64]
    float* attn   = result + (size_t)BATCH * TSEQ * DK;             // [64,1024,1024]

    const int smem1 = SMEM1_FLOATS * (int)sizeof(float);
    cudaFuncSetAttribute(attn_softmax_kernel,
                         cudaFuncAttributeMaxDynamicSharedMemorySize, smem1);
    const int smem2 = SMEM2_FLOATS * (int)sizeof(float);
    cudaFuncSetAttribute(av_kernel,
                         cudaFuncAttributeMaxDynamicSharedMemorySize, smem2);

    dim3 grid1(TSEQ / K1_Q, BATCH);
    attn_softmax_kernel<<<grid1, 512, smem1>>>(key, query, mask, qmask, gf, attn);

    dim3 grid2(TSEQ / 128, BATCH);
    av_kernel<<<grid2, 256, smem2>>>(value, attn, result);
}